// round 1
// baseline (speedup 1.0000x reference)
#include <cuda_runtime.h>
#include <cstdint>

// Problem constants (fixed shapes from reference: x[128,256,32,32], w[1,256], TOPK=64)
#define NB   128
#define CCH  256
#define HW   1024
#define TOPK 64

// One block per batch row n. 1024 threads; thread tid owns spatial position s=tid.
__global__ __launch_bounds__(1024, 1)
void fused_topk_kernel(const float* __restrict__ x, const float* __restrict__ w,
                       float* __restrict__ concat_out,   // [NB, TOPK*CCH + HW] or null
                       float* __restrict__ st_mask_out,  // [NB, HW] or null
                       float* __restrict__ out_full)     // [NB, CCH, HW] or null
{
    const int n    = blockIdx.x;
    const int tid  = threadIdx.x;
    const int lane = tid & 31;
    const int warp = tid >> 5;
    const float* xn = x + (size_t)n * (CCH * (size_t)HW);

    __shared__ float sw[CCH];
    __shared__ float sst[HW];
    __shared__ float sred[32];
    __shared__ int   wcnt[32];
    __shared__ int   sidx[TOPK];
    __shared__ float sbcast[2];

    if (tid < CCH) sw[tid] = w[tid];
    __syncthreads();

    // ---- Pass 1: logits[n, tid] = sum_c x[n,c,tid] * w[c]  (coalesced stream of x) ----
    float acc = 0.f;
    #pragma unroll 8
    for (int c = 0; c < CCH; ++c)
        acc = fmaf(xn[(size_t)c * HW + tid], sw[c], acc);

    // ---- Row max (softmax stability) ----
    float v = acc;
    #pragma unroll
    for (int o = 16; o; o >>= 1) v = fmaxf(v, __shfl_xor_sync(0xffffffffu, v, o));
    if (lane == 0) sred[warp] = v;
    __syncthreads();
    if (warp == 0) {
        float t = sred[lane];
        #pragma unroll
        for (int o = 16; o; o >>= 1) t = fmaxf(t, __shfl_xor_sync(0xffffffffu, t, o));
        if (lane == 0) sbcast[0] = t;
    }
    __syncthreads();
    const float rowmax = sbcast[0];

    // ---- exp and sum ----
    const float e = __expf(acc - rowmax);
    v = e;
    #pragma unroll
    for (int o = 16; o; o >>= 1) v += __shfl_xor_sync(0xffffffffu, v, o);
    __syncthreads();                 // sred reuse: prior phase fully consumed
    if (lane == 0) sred[warp] = v;
    __syncthreads();
    if (warp == 0) {
        float t = sred[lane];
        #pragma unroll
        for (int o = 16; o; o >>= 1) t += __shfl_xor_sync(0xffffffffu, t, o);
        if (lane == 0) sbcast[1] = t;
    }
    __syncthreads();
    const float p = e / sbcast[1];

    // ---- Top-64 selection on logits (monotonic with p). Exact 64th-largest key via
    //      32-round bitwise radix-select using the hardware block-count barrier. ----
    const unsigned ub  = __float_as_uint(acc);
    const unsigned key = (ub & 0x80000000u) ? ~ub : (ub | 0x80000000u);
    unsigned prefix = 0;
    #pragma unroll 1
    for (int bit = 31; bit >= 0; --bit) {
        const unsigned trial  = prefix | (1u << bit);
        const unsigned himask = ~((1u << bit) - 1u);
        const int cnt = __syncthreads_count((key & himask) >= trial);
        if (cnt >= TOPK) prefix = trial;
    }
    const unsigned V = prefix;                  // exact 64th-largest key value
    const int gt    = key > V;
    const int cntGt = __syncthreads_count(gt);  // < TOPK by construction
    const int need  = TOPK - cntGt;
    const int eq    = (key == V);

    // equal-key rank over tid (lowest index wins ties, matching jax.lax.top_k)
    unsigned b = __ballot_sync(0xffffffffu, eq);
    if (lane == 0) wcnt[warp] = __popc(b);
    __syncthreads();
    int off = 0;
    for (int k = 0; k < warp; ++k) off += wcnt[k];
    const int eqrank = off + __popc(b & ((1u << lane) - 1u));
    const int sel = gt || (eq && eqrank < need);
    __syncthreads();

    // exclusive prefix over sel -> slot (ascending-index order, matching sorted idx)
    b = __ballot_sync(0xffffffffu, sel);
    if (lane == 0) wcnt[warp] = __popc(b);
    __syncthreads();
    off = 0;
    for (int k = 0; k < warp; ++k) off += wcnt[k];
    const int slot = off + __popc(b & ((1u << lane) - 1u));

    // straight-through value: exactly (mask - p) + p in fp32 (0 exactly off-mask)
    const float m  = sel ? 1.0f : 0.0f;
    const float st = (m - p) + p;
    sst[tid] = st;
    if (sel) sidx[slot] = tid;
    __syncthreads();

    // ---- Small outputs ----
    if (st_mask_out)
        st_mask_out[(size_t)n * HW + tid] = st;

    const size_t cbase = (size_t)n * (TOPK * CCH + HW);
    if (concat_out) {
        concat_out[cbase + TOPK * CCH + tid] = st;   // st tail of concat row

        // gather: out_efficient[t, c] = st[idx_t] * x[n, c, idx_t]
        // x[n] was just streamed by this block -> L2-hot scattered reads; coalesced writes.
        const int c = tid & (CCH - 1);
        #pragma unroll
        for (int t = tid >> 8; t < TOPK; t += 4) {
            const int s = sidx[t];
            concat_out[cbase + (size_t)t * CCH + c] = sst[s] * xn[(size_t)c * HW + s];
        }
    }

    // ---- Pass 2: out = st * x  (streaming; evict-first hints, last use of xn) ----
    if (out_full) {
        float* on = out_full + (size_t)n * (CCH * (size_t)HW);
        #pragma unroll 4
        for (int c = 0; c < CCH; ++c) {
            const float xv = __ldcs(&xn[(size_t)c * HW + tid]);
            __stcs(&on[(size_t)c * HW + tid], st * xv);
        }
    }
}

extern "C" void kernel_launch(void* const* d_in, const int* in_sizes, int n_in,
                              void* d_out, int out_size)
{
    const float* x = (const float*)d_in[0];
    const float* w = (const float*)d_in[1];
    // Defensive: detect input ordering by element counts (x has 33.5M, w has 256).
    if (n_in >= 2 && in_sizes[0] == CCH && in_sizes[1] > CCH) {
        x = (const float*)d_in[1];
        w = (const float*)d_in[0];
    }

    const long long SZ_CONCAT = (long long)NB * (TOPK * CCH + HW);   // 2,228,224
    const long long SZ_MASK   = (long long)NB * HW;                  //   131,072
    const long long SZ_OUT    = (long long)NB * CCH * HW;            // 33,554,432
    const long long os = (long long)out_size;

    float* base = (float*)d_out;
    float* pc = nullptr; float* pm = nullptr; float* po = nullptr;

    if (os == SZ_CONCAT + SZ_MASK + SZ_OUT) {
        pc = base; pm = base + SZ_CONCAT; po = base + SZ_CONCAT + SZ_MASK;
    } else if (os == SZ_CONCAT + SZ_MASK) {
        pc = base; pm = base + SZ_CONCAT;
    } else if (os == SZ_CONCAT + SZ_OUT) {
        pc = base; po = base + SZ_CONCAT;
    } else if (os == SZ_CONCAT) {
        pc = base;
    } else if (os == SZ_OUT) {
        po = base;
    } else if (os == SZ_MASK) {
        pm = base;
    } else {
        // Fallback: assume concat first, append what fits.
        pc = base;
        if (os >= SZ_CONCAT + SZ_MASK) pm = base + SZ_CONCAT;
        if (os >= SZ_CONCAT + SZ_MASK + SZ_OUT) po = base + SZ_CONCAT + SZ_MASK;
    }

    fused_topk_kernel<<<NB, 1024>>>(x, w, pc, pm, po);
}

// round 2
// speedup vs baseline: 2.2853x; 2.2853x over previous
#include <cuda_runtime.h>
#include <cstdint>

// Fixed shapes: x[128,256,32,32] fp32, w[1,256], TOPK=64
#define NB   128
#define CCH  256
#define HW   1024
#define TOPK 64
#define Q4   (HW/4)        // 256 float4 per channel row

// Inter-kernel scratch (allocation-free: __device__ globals)
__device__ float g_st[NB * HW];
__device__ int   g_sidx[NB * TOPK];

// ============================================================================
// Kernel A: logits (1x1 conv) + softmax + exact top-64 + st values.
// 128 blocks x 1024 threads. 4-way channel split x float4 spatial -> 16B loads.
// Thread tid: cg = tid>>8 handles channels [cg*64, cg*64+64), q = tid&255 is
// the float4 spatial index (positions 4q..4q+3).
// ============================================================================
__global__ __launch_bounds__(1024, 1)
void k_logits_topk(const float4* __restrict__ x4, const float* __restrict__ w,
                   float* __restrict__ concat_out,   // st tail written here (or null)
                   float* __restrict__ st_mask_out)  // [NB,HW] (or null)
{
    const int n    = blockIdx.x;
    const int tid  = threadIdx.x;
    const int lane = tid & 31;
    const int warp = tid >> 5;
    const int cg   = tid >> 8;
    const int q    = tid & 255;
    const float4* xn4 = x4 + (size_t)n * (CCH * Q4);

    __shared__ float  sw[CCH];
    __shared__ float4 spart[4][Q4];   // partial dot per channel-group
    __shared__ float  sred[32];
    __shared__ int    wcnt[32];
    __shared__ float  sb[2];

    if (tid < CCH) sw[tid] = w[tid];
    __syncthreads();

    // ---- partial logits: 64 channels per thread, float4 spatial ----
    float4 a = make_float4(0.f, 0.f, 0.f, 0.f);
    const int c0 = cg * 64;
    #pragma unroll 8
    for (int k = 0; k < 64; ++k) {
        const int c = c0 + k;
        const float4 xv = __ldcs(&xn4[c * Q4 + q]);
        const float  wc = sw[c];
        a.x = fmaf(xv.x, wc, a.x);
        a.y = fmaf(xv.y, wc, a.y);
        a.z = fmaf(xv.z, wc, a.z);
        a.w = fmaf(xv.w, wc, a.w);
    }
    spart[cg][q] = a;
    __syncthreads();

    // reduce the 4 channel-group partials; thread tid owns spatial position tid
    const float* sp = (const float*)spart;
    const float acc = (sp[tid] + sp[HW + tid]) + (sp[2 * HW + tid] + sp[3 * HW + tid]);

    // ---- row max ----
    float v = acc;
    #pragma unroll
    for (int o = 16; o; o >>= 1) v = fmaxf(v, __shfl_xor_sync(0xffffffffu, v, o));
    if (lane == 0) sred[warp] = v;
    __syncthreads();
    if (warp == 0) {
        float t = sred[lane];
        #pragma unroll
        for (int o = 16; o; o >>= 1) t = fmaxf(t, __shfl_xor_sync(0xffffffffu, t, o));
        if (lane == 0) sb[0] = t;
    }
    __syncthreads();
    const float rowmax = sb[0];

    // ---- exp & sum ----
    const float e = __expf(acc - rowmax);
    v = e;
    #pragma unroll
    for (int o = 16; o; o >>= 1) v += __shfl_xor_sync(0xffffffffu, v, o);
    __syncthreads();
    if (lane == 0) sred[warp] = v;
    __syncthreads();
    if (warp == 0) {
        float t = sred[lane];
        #pragma unroll
        for (int o = 16; o; o >>= 1) t += __shfl_xor_sync(0xffffffffu, t, o);
        if (lane == 0) sb[1] = t;
    }
    __syncthreads();
    const float p = e / sb[1];

    // ---- exact 64th-largest key via 32-round radix select on logits ----
    const unsigned ub  = __float_as_uint(acc);
    const unsigned key = (ub & 0x80000000u) ? ~ub : (ub | 0x80000000u);
    unsigned prefix = 0;
    #pragma unroll 1
    for (int bit = 31; bit >= 0; --bit) {
        const unsigned trial  = prefix | (1u << bit);
        const unsigned himask = ~((1u << bit) - 1u);
        const int cnt = __syncthreads_count((key & himask) >= trial);
        if (cnt >= TOPK) prefix = trial;
    }
    const unsigned V = prefix;
    const int gt    = key > V;
    const int cntGt = __syncthreads_count(gt);
    const int need  = TOPK - cntGt;
    const int eq    = (key == V);

    // equal-key rank (lowest index wins ties, matching jax.lax.top_k)
    unsigned b = __ballot_sync(0xffffffffu, eq);
    if (lane == 0) wcnt[warp] = __popc(b);
    __syncthreads();
    int off = 0;
    for (int k = 0; k < warp; ++k) off += wcnt[k];
    const int eqrank = off + __popc(b & ((1u << lane) - 1u));
    const int sel = gt || (eq && eqrank < need);
    __syncthreads();

    // exclusive prefix over sel -> ascending-index slot
    b = __ballot_sync(0xffffffffu, sel);
    if (lane == 0) wcnt[warp] = __popc(b);
    __syncthreads();
    off = 0;
    for (int k = 0; k < warp; ++k) off += wcnt[k];
    const int slot = off + __popc(b & ((1u << lane) - 1u));

    // straight-through value: exactly (mask - p) + p in fp32
    const float m  = sel ? 1.0f : 0.0f;
    const float st = (m - p) + p;

    g_st[(size_t)n * HW + tid] = st;
    if (sel) g_sidx[n * TOPK + slot] = tid;

    if (st_mask_out) st_mask_out[(size_t)n * HW + tid] = st;
    if (concat_out)  concat_out[(size_t)n * (TOPK * CCH + HW) + TOPK * CCH + tid] = st;
}

// ============================================================================
// Kernel C: out = st * x (streaming, float4) + fused top-k gather via SMEM tile.
// Grid (NB, 4): block handles 64 channels of one n. 1024 threads.
// ============================================================================
__global__ __launch_bounds__(1024, 2)
void k_stream_gather(const float4* __restrict__ x4,
                     float* __restrict__ concat_out,   // or null
                     float4* __restrict__ out4)        // or null
{
    const int n   = blockIdx.x;
    const int cg  = blockIdx.y;
    const int tid = threadIdx.x;

    __shared__ float4      sst4[Q4];        // st per float4 of spatial positions
    __shared__ signed char slot[HW];        // spatial pos -> topk slot (or -1)
    __shared__ float       gath[TOPK * 65]; // padded [64][65] gather tile

    if (tid < Q4) {
        sst4[tid] = ((const float4*)g_st)[n * Q4 + tid];
        ((int*)slot)[tid] = -1;   // 0xFFFFFFFF = four -1 bytes
    }
    __syncthreads();
    if (tid < TOPK) slot[g_sidx[n * TOPK + tid]] = (signed char)tid;
    __syncthreads();

    const size_t nbase = (size_t)n * (CCH * Q4);
    const int q   = tid & 255;
    const int cl0 = tid >> 8;

    #pragma unroll
    for (int it = 0; it < 16; ++it) {
        const int cl = it * 4 + cl0;          // local channel 0..63
        const int c  = cg * 64 + cl;
        const float4 xv = __ldcs(&x4[nbase + c * Q4 + q]);
        const float4 sv = sst4[q];
        float4 ov;
        ov.x = xv.x * sv.x;
        ov.y = xv.y * sv.y;
        ov.z = xv.z * sv.z;
        ov.w = xv.w * sv.w;
        if (out4) __stcs(&out4[nbase + c * Q4 + q], ov);

        const char4 sl = ((const char4*)slot)[q];   // slots for positions 4q..4q+3
        if (sl.x >= 0) gath[(int)sl.x * 65 + cl] = ov.x;
        if (sl.y >= 0) gath[(int)sl.y * 65 + cl] = ov.y;
        if (sl.z >= 0) gath[(int)sl.z * 65 + cl] = ov.z;
        if (sl.w >= 0) gath[(int)sl.w * 65 + cl] = ov.w;
    }

    if (concat_out) {
        __syncthreads();
        const size_t cbase = (size_t)n * (TOPK * CCH + HW);
        #pragma unroll
        for (int k = 0; k < 4; ++k) {
            const int e  = tid + k * 1024;    // 0..4095
            const int t  = e >> 6;
            const int cl = e & 63;
            concat_out[cbase + t * CCH + cg * 64 + cl] = gath[t * 65 + cl];
        }
    }
}

extern "C" void kernel_launch(void* const* d_in, const int* in_sizes, int n_in,
                              void* d_out, int out_size)
{
    const float* x = (const float*)d_in[0];
    const float* w = (const float*)d_in[1];
    if (n_in >= 2 && in_sizes[0] == CCH && in_sizes[1] > CCH) {
        x = (const float*)d_in[1];
        w = (const float*)d_in[0];
    }

    const long long SZ_CONCAT = (long long)NB * (TOPK * CCH + HW);
    const long long SZ_MASK   = (long long)NB * HW;
    const long long SZ_OUT    = (long long)NB * CCH * HW;
    const long long os = (long long)out_size;

    float* base = (float*)d_out;
    float* pc = nullptr; float* pm = nullptr; float* po = nullptr;

    if (os == SZ_CONCAT + SZ_MASK + SZ_OUT) {
        pc = base; pm = base + SZ_CONCAT; po = base + SZ_CONCAT + SZ_MASK;
    } else if (os == SZ_CONCAT + SZ_MASK) {
        pc = base; pm = base + SZ_CONCAT;
    } else if (os == SZ_CONCAT + SZ_OUT) {
        pc = base; po = base + SZ_CONCAT;
    } else if (os == SZ_CONCAT) {
        pc = base;
    } else if (os == SZ_OUT) {
        po = base;
    } else if (os == SZ_MASK) {
        pm = base;
    } else {
        pc = base;
        if (os >= SZ_CONCAT + SZ_MASK) pm = base + SZ_CONCAT;
        if (os >= SZ_CONCAT + SZ_MASK + SZ_OUT) po = base + SZ_CONCAT + SZ_MASK;
    }

    k_logits_topk<<<NB, 1024>>>((const float4*)x, w, pc, pm);
    if (pc || po)
        k_stream_gather<<<dim3(NB, 4), 1024>>>((const float4*)x, pc, (float4*)po);
}